// round 1
// baseline (speedup 1.0000x reference)
#include <cuda_runtime.h>
#include <cstdint>

#define N_NODES 8192
#define DIM_EMB 256
#define HIDDEN  128
#define OUTC    64

// ---------------- scratch (device globals; no allocs allowed) ----------------
__device__ __align__(128) float g_d [N_NODES];
__device__ __align__(128) float g_C1[N_NODES * HIDDEN];  // d ⊙ (x @ W1)
__device__ __align__(128) float g_h [N_NODES * HIDDEN];  // relu(d*Z1 + b1)
__device__ __align__(128) float g_C2[N_NODES * OUTC];    // d ⊙ (h @ W2)

// ---------------- pass 1: d[i] = rsqrt(sum_j adj[i][j]) ----------------
__global__ void rowsum_rsqrt(const float* __restrict__ adj, float* __restrict__ dvec) {
    const int row = blockIdx.x;
    const float4* p = reinterpret_cast<const float4*>(adj + (size_t)row * N_NODES);
    float s = 0.f;
    for (int i = threadIdx.x; i < N_NODES / 4; i += 256) {
        float4 v = p[i];
        s += (v.x + v.y) + (v.z + v.w);
    }
    #pragma unroll
    for (int o = 16; o > 0; o >>= 1) s += __shfl_down_sync(0xffffffffu, s, o);
    __shared__ float red[8];
    if ((threadIdx.x & 31) == 0) red[threadIdx.x >> 5] = s;
    __syncthreads();
    if (threadIdx.x < 8) {
        s = red[threadIdx.x];
        #pragma unroll
        for (int o = 4; o > 0; o >>= 1) s += __shfl_down_sync(0xffu, s, o);
        if (threadIdx.x == 0) dvec[row] = rsqrtf(s);
    }
}

// ---------------- small GEMM: out[j][n] = d[j] * sum_k X[j][k]*W[k][n] -------
template<int K, int NC>
__global__ void small_gemm_scale(const float* __restrict__ X,
                                 const float* __restrict__ W,
                                 const float* __restrict__ dvec,
                                 float* __restrict__ out) {
    __shared__ float xs[16 * K];
    const int r0 = blockIdx.x * 16;
    const float4* xsrc = reinterpret_cast<const float4*>(X + (size_t)r0 * K);
    float4* xdst = reinterpret_cast<float4*>(xs);
    for (int i = threadIdx.x; i < 4 * K; i += NC) xdst[i] = xsrc[i];
    __syncthreads();

    const int n = threadIdx.x;
    float acc[16];
    #pragma unroll
    for (int r = 0; r < 16; ++r) acc[r] = 0.f;

    for (int k = 0; k < K; ++k) {
        const float w = W[k * NC + n];
        #pragma unroll
        for (int r = 0; r < 16; ++r) acc[r] = fmaf(xs[r * K + k], w, acc[r]);
    }
    #pragma unroll
    for (int r = 0; r < 16; ++r)
        out[(size_t)(r0 + r) * NC + n] = dvec[r0 + r] * acc[r];
}

// ---------------- big GEMM: Z[m][n] = sum_k adj[k][m] * Y[k][n] --------------
// 3xTF32 (hi/lo split) on mma.sync.m16n8k8, double-buffered cp.async.
// Epilogue: out = (relu?)(d[m]*Z + bias[n]).

__device__ __forceinline__ void cp_async16(void* smem_dst, const void* gsrc) {
    uint32_t s = (uint32_t)__cvta_generic_to_shared(smem_dst);
    asm volatile("cp.async.cg.shared.global [%0], [%1], 16;\n" :: "r"(s), "l"(gsrc));
}
__device__ __forceinline__ void cp_commit() {
    asm volatile("cp.async.commit_group;\n" ::: "memory");
}
__device__ __forceinline__ void cp_wait1() {
    asm volatile("cp.async.wait_group 1;\n" ::: "memory");
}
__device__ __forceinline__ void cp_wait0() {
    asm volatile("cp.async.wait_group 0;\n" ::: "memory");
}

// fp32 -> tf32 hi (rounded) + residual lo (truncated by HW; err ~2^-20)
__device__ __forceinline__ void split_f32(float f, uint32_t& hi, uint32_t& lo) {
    uint32_t h;
    asm("cvt.rna.tf32.f32 %0, %1;" : "=r"(h) : "f"(f));
    hi = h;
    lo = __float_as_uint(f - __uint_as_float(h));
}

__device__ __forceinline__ void mma_tf32(float* c, const uint32_t* a, const uint32_t* b) {
    asm volatile(
        "mma.sync.aligned.m16n8k8.row.col.f32.tf32.tf32.f32 "
        "{%0,%1,%2,%3}, {%4,%5,%6,%7}, {%8,%9}, {%0,%1,%2,%3};"
        : "+f"(c[0]), "+f"(c[1]), "+f"(c[2]), "+f"(c[3])
        : "r"(a[0]), "r"(a[1]), "r"(a[2]), "r"(a[3]), "r"(b[0]), "r"(b[1]));
}

template<int NC, bool RELU>
__global__ void __launch_bounds__(256, 1)
big_gemm(const float* __restrict__ adj,     // [8192][8192], used as adj^T
         const float* __restrict__ Y,       // [8192][NC]
         const float* __restrict__ dvec,
         const float* __restrict__ bias,    // [NC]
         float* __restrict__ out) {         // [8192][NC]
    constexpr int KC  = 16;                 // k-chunk
    constexpr int MT  = 64;                 // CTA m-tile
    constexpr int AP  = 72;                 // A smem stride (72 % 32 == 8: conflict-free frags)
    constexpr int BP  = NC + 8;             // B smem stride (also % 32 == 8)
    constexpr int NT  = NC / 32;            // n8-tiles per warp (warp covers 8*NT cols)
    constexpr int NCH = N_NODES / KC;       // 512 chunks

    __shared__ float As[2][KC][AP];
    __shared__ float Bs[2][KC][BP];

    const int tid  = threadIdx.x;
    const int lane = tid & 31;
    const int wid  = tid >> 5;
    const int wm   = wid & 1;   // 2 warps over M
    const int wn   = wid >> 1;  // 4 warps over N
    const int g    = lane >> 2; // groupID
    const int q    = lane & 3;  // threadID in group
    const int m0   = blockIdx.x * MT;

    float acc[2][NT][4];
    #pragma unroll
    for (int mt = 0; mt < 2; ++mt)
        #pragma unroll
        for (int nt = 0; nt < NT; ++nt)
            #pragma unroll
            for (int i = 0; i < 4; ++i) acc[mt][nt][i] = 0.f;

    auto load_chunk = [&](int c, int buf) {
        // A tile: adj rows [c*KC, c*KC+16), cols [m0, m0+64). 16 rows x 16 float4.
        {
            const int r = tid >> 4, c4 = tid & 15;
            cp_async16(&As[buf][r][c4 * 4],
                       adj + (size_t)(c * KC + r) * N_NODES + m0 + c4 * 4);
        }
        // B tile: Y rows [c*KC, c*KC+16), all NC cols.
        const float* yp = Y + (size_t)(c * KC) * NC;
        #pragma unroll
        for (int p = 0; p < NC / 64; ++p) {
            const int idx = tid + p * 256;
            const int r = idx / (NC / 4), c4 = idx % (NC / 4);
            cp_async16(&Bs[buf][r][c4 * 4], yp + r * NC + c4 * 4);
        }
        cp_commit();
    };

    load_chunk(0, 0);

    for (int c = 0; c < NCH; ++c) {
        if (c + 1 < NCH) {
            load_chunk(c + 1, (c + 1) & 1);
            cp_wait1();
        } else {
            cp_wait0();
        }
        __syncthreads();

        const int buf = c & 1;
        #pragma unroll
        for (int ks = 0; ks < KC; ks += 8) {
            uint32_t ahi[2][4], alo[2][4];
            #pragma unroll
            for (int mt = 0; mt < 2; ++mt) {
                const int mb = wm * 32 + mt * 16;
                split_f32(As[buf][ks + q    ][mb + g    ], ahi[mt][0], alo[mt][0]);
                split_f32(As[buf][ks + q    ][mb + g + 8], ahi[mt][1], alo[mt][1]);
                split_f32(As[buf][ks + q + 4][mb + g    ], ahi[mt][2], alo[mt][2]);
                split_f32(As[buf][ks + q + 4][mb + g + 8], ahi[mt][3], alo[mt][3]);
            }
            uint32_t bhi[NT][2], blo[NT][2];
            #pragma unroll
            for (int nt = 0; nt < NT; ++nt) {
                const int nb = wn * (8 * NT) + nt * 8 + g;
                split_f32(Bs[buf][ks + q    ][nb], bhi[nt][0], blo[nt][0]);
                split_f32(Bs[buf][ks + q + 4][nb], bhi[nt][1], blo[nt][1]);
            }
            #pragma unroll
            for (int mt = 0; mt < 2; ++mt)
                #pragma unroll
                for (int nt = 0; nt < NT; ++nt) {
                    mma_tf32(acc[mt][nt], alo[mt], bhi[nt]);  // lo*hi
                    mma_tf32(acc[mt][nt], ahi[mt], blo[nt]);  // hi*lo
                    mma_tf32(acc[mt][nt], ahi[mt], bhi[nt]);  // hi*hi
                }
        }
        __syncthreads();
    }

    // ---- epilogue: out[m][n] = (relu?)(d[m]*acc + bias[n]) ----
    #pragma unroll
    for (int mt = 0; mt < 2; ++mt) {
        const int m = m0 + wm * 32 + mt * 16 + g;
        const float d0 = dvec[m], d1 = dvec[m + 8];
        #pragma unroll
        for (int nt = 0; nt < NT; ++nt) {
            const int n = wn * (8 * NT) + nt * 8 + 2 * q;
            const float bn0 = bias[n], bn1 = bias[n + 1];
            float v00 = fmaf(d0, acc[mt][nt][0], bn0);
            float v01 = fmaf(d0, acc[mt][nt][1], bn1);
            float v10 = fmaf(d1, acc[mt][nt][2], bn0);
            float v11 = fmaf(d1, acc[mt][nt][3], bn1);
            if (RELU) {
                v00 = fmaxf(v00, 0.f); v01 = fmaxf(v01, 0.f);
                v10 = fmaxf(v10, 0.f); v11 = fmaxf(v11, 0.f);
            }
            out[(size_t)m * NC + n]           = v00;
            out[(size_t)m * NC + n + 1]       = v01;
            out[(size_t)(m + 8) * NC + n]     = v10;
            out[(size_t)(m + 8) * NC + n + 1] = v11;
        }
    }
}

// ---------------- launch ----------------
extern "C" void kernel_launch(void* const* d_in, const int* in_sizes, int n_in,
                              void* d_out, int out_size) {
    const float* x   = (const float*)d_in[0];  // [8192, 256]
    const float* adj = (const float*)d_in[1];  // [8192, 8192]
    const float* W1  = (const float*)d_in[2];  // [256, 128]
    const float* b1  = (const float*)d_in[3];  // [128]
    const float* W2  = (const float*)d_in[4];  // [128, 64]
    const float* b2  = (const float*)d_in[5];  // [64]
    float* out = (float*)d_out;                // [8192, 64]

    float *pd, *pC1, *ph, *pC2;
    cudaGetSymbolAddress((void**)&pd,  g_d);
    cudaGetSymbolAddress((void**)&pC1, g_C1);
    cudaGetSymbolAddress((void**)&ph,  g_h);
    cudaGetSymbolAddress((void**)&pC2, g_C2);

    // 1. d = rsqrt(rowsum(adj))
    rowsum_rsqrt<<<N_NODES, 256>>>(adj, pd);
    // 2. C1' = d ⊙ (x @ W1)
    small_gemm_scale<DIM_EMB, HIDDEN><<<N_NODES / 16, HIDDEN>>>(x, W1, pd, pC1);
    // 3. h = relu(d ⊙ (adj^T @ C1') + b1)
    big_gemm<HIDDEN, true><<<N_NODES / 64, 256>>>(adj, pC1, pd, b1, ph);
    // 4. C2' = d ⊙ (h @ W2)
    small_gemm_scale<HIDDEN, OUTC><<<N_NODES / 16, OUTC>>>(ph, W2, pd, pC2);
    // 5. out = d ⊙ (adj^T @ C2') + b2
    big_gemm<OUTC, false><<<N_NODES / 64, 256>>>(adj, pC2, pd, b2, out);
}

// round 3
// speedup vs baseline: 1.0743x; 1.0743x over previous
#include <cuda_runtime.h>
#include <cstdint>

#define N_NODES 8192
#define DIM_EMB 256
#define HIDDEN  128
#define OUTC    64

// ---------------- scratch (device globals; no allocs allowed) ----------------
__device__ __align__(128) float g_d [N_NODES];
__device__ __align__(128) float g_C1[N_NODES * HIDDEN];  // d ⊙ (x @ W1)
__device__ __align__(128) float g_h [N_NODES * HIDDEN];  // relu(d*Z1 + b1)
__device__ __align__(128) float g_C2[N_NODES * OUTC];    // d ⊙ (h @ W2)

// ---------------- pass 1: d[i] = rsqrt(sum_j adj[i][j]) ----------------
__global__ void rowsum_rsqrt(const float* __restrict__ adj, float* __restrict__ dvec) {
    const int row = blockIdx.x;
    const float4* p = reinterpret_cast<const float4*>(adj + (size_t)row * N_NODES);
    float s = 0.f;
    for (int i = threadIdx.x; i < N_NODES / 4; i += 256) {
        float4 v = p[i];
        s += (v.x + v.y) + (v.z + v.w);
    }
    #pragma unroll
    for (int o = 16; o > 0; o >>= 1) s += __shfl_down_sync(0xffffffffu, s, o);
    __shared__ float red[8];
    if ((threadIdx.x & 31) == 0) red[threadIdx.x >> 5] = s;
    __syncthreads();
    if (threadIdx.x < 8) {
        s = red[threadIdx.x];
        #pragma unroll
        for (int o = 4; o > 0; o >>= 1) s += __shfl_down_sync(0xffu, s, o);
        if (threadIdx.x == 0) dvec[row] = rsqrtf(s);
    }
}

// ---------------- small GEMM: out[j][n] = d[j] * sum_k X[j][k]*W[k][n] -------
template<int K, int NC>
__global__ void small_gemm_scale(const float* __restrict__ X,
                                 const float* __restrict__ W,
                                 const float* __restrict__ dvec,
                                 float* __restrict__ out) {
    __shared__ float xs[16 * K];
    const int r0 = blockIdx.x * 16;
    const float4* xsrc = reinterpret_cast<const float4*>(X + (size_t)r0 * K);
    float4* xdst = reinterpret_cast<float4*>(xs);
    for (int i = threadIdx.x; i < 4 * K; i += NC) xdst[i] = xsrc[i];
    __syncthreads();

    const int n = threadIdx.x;
    float acc[16];
    #pragma unroll
    for (int r = 0; r < 16; ++r) acc[r] = 0.f;

    for (int k = 0; k < K; ++k) {
        const float w = W[k * NC + n];
        #pragma unroll
        for (int r = 0; r < 16; ++r) acc[r] = fmaf(xs[r * K + k], w, acc[r]);
    }
    #pragma unroll
    for (int r = 0; r < 16; ++r)
        out[(size_t)(r0 + r) * NC + n] = dvec[r0 + r] * acc[r];
}

// ---------------- big GEMM: Z[m][n] = sum_k adj[k][m] * Y[k][n] --------------
// 3xTF32 (hi/lo split) on mma.sync.m16n8k8; 4-stage cp.async pipeline, KC=32.
// Epilogue: out = (relu?)(d[m]*Z + bias[n]).

__device__ __forceinline__ void cp_async16(void* smem_dst, const void* gsrc) {
    uint32_t s = (uint32_t)__cvta_generic_to_shared(smem_dst);
    asm volatile("cp.async.cg.shared.global [%0], [%1], 16;\n" :: "r"(s), "l"(gsrc));
}
__device__ __forceinline__ void cp_commit() {
    asm volatile("cp.async.commit_group;\n" ::: "memory");
}
__device__ __forceinline__ void cp_wait2() {
    asm volatile("cp.async.wait_group 2;\n" ::: "memory");
}

// fp32 -> tf32 hi (rounded) + residual lo
__device__ __forceinline__ void split_f32(float f, uint32_t& hi, uint32_t& lo) {
    uint32_t h;
    asm("cvt.rna.tf32.f32 %0, %1;" : "=r"(h) : "f"(f));
    hi = h;
    lo = __float_as_uint(f - __uint_as_float(h));
}

__device__ __forceinline__ void mma_tf32(float* c, const uint32_t* a, const uint32_t* b) {
    asm volatile(
        "mma.sync.aligned.m16n8k8.row.col.f32.tf32.tf32.f32 "
        "{%0,%1,%2,%3}, {%4,%5,%6,%7}, {%8,%9}, {%0,%1,%2,%3};"
        : "+f"(c[0]), "+f"(c[1]), "+f"(c[2]), "+f"(c[3])
        : "r"(a[0]), "r"(a[1]), "r"(a[2]), "r"(a[3]), "r"(b[0]), "r"(b[1]));
}

template<int NC, bool RELU>
__global__ void __launch_bounds__(256, 1)
big_gemm(const float* __restrict__ adj,     // [8192][8192], used as adj^T
         const float* __restrict__ Y,       // [8192][NC]
         const float* __restrict__ dvec,
         const float* __restrict__ bias,    // [NC]
         float* __restrict__ out) {         // [8192][NC]
    constexpr int KC  = 32;                 // k-chunk
    constexpr int ST  = 4;                  // pipeline stages
    constexpr int MT  = 64;                 // CTA m-tile
    constexpr int AP  = 72;                 // A smem stride (72 % 32 == 8: conflict-free)
    constexpr int BP  = NC + 8;             // B smem stride (also % 32 == 8)
    constexpr int NT  = NC / 32;            // n8-tiles per warp
    constexpr int NCH = N_NODES / KC;       // 256 chunks

    extern __shared__ float smbuf[];
    float* As = smbuf;                      // ST * KC * AP
    float* Bs = smbuf + ST * KC * AP;       // ST * KC * BP

    const int tid  = threadIdx.x;
    const int lane = tid & 31;
    const int wid  = tid >> 5;
    const int wm   = wid & 1;   // 2 warps over M
    const int wn   = wid >> 1;  // 4 warps over N
    const int g    = lane >> 2; // groupID
    const int q    = lane & 3;  // threadID in group
    const int m0   = blockIdx.x * MT;

    float acc[2][NT][4];
    #pragma unroll
    for (int mt = 0; mt < 2; ++mt)
        #pragma unroll
        for (int nt = 0; nt < NT; ++nt)
            #pragma unroll
            for (int i = 0; i < 4; ++i) acc[mt][nt][i] = 0.f;

    auto load_chunk = [&](int c, int buf) {
        // A tile: adj rows [c*KC, c*KC+32), cols [m0, m0+64): 32 rows x 16 float4.
        float* a = As + buf * (KC * AP);
        #pragma unroll
        for (int p = 0; p < 2; ++p) {
            const int idx = tid + p * 256;
            const int r = idx >> 4, c4 = idx & 15;
            cp_async16(a + r * AP + c4 * 4,
                       adj + (size_t)(c * KC + r) * N_NODES + m0 + c4 * 4);
        }
        // B tile: Y rows [c*KC, c*KC+32), all NC cols: 32 * NC/4 float4.
        float* b = Bs + buf * (KC * BP);
        const float* yp = Y + (size_t)(c * KC) * NC;
        #pragma unroll
        for (int p = 0; p < NC / 32; ++p) {
            const int idx = tid + p * 256;
            const int r = idx / (NC / 4), c4 = idx % (NC / 4);
            cp_async16(b + r * BP + c4 * 4, yp + r * NC + c4 * 4);
        }
    };

    // prologue: 3 chunks in flight
    load_chunk(0, 0); cp_commit();
    load_chunk(1, 1); cp_commit();
    load_chunk(2, 2); cp_commit();

    for (int c = 0; c < NCH; ++c) {
        cp_wait2();          // with 3 groups pending, retires chunk c's group
        __syncthreads();     // chunk-c data visible; all warps done with c-1

        if (c + 3 < NCH) load_chunk(c + 3, (c + 3) & (ST - 1));
        cp_commit();         // empty group at tail keeps counting uniform

        const int buf = c & (ST - 1);
        const float* a = As + buf * (KC * AP);
        const float* b = Bs + buf * (KC * BP);
        #pragma unroll
        for (int ks = 0; ks < KC; ks += 8) {
            uint32_t ahi[2][4], alo[2][4];
            #pragma unroll
            for (int mt = 0; mt < 2; ++mt) {
                const int mb = wm * 32 + mt * 16;
                split_f32(a[(ks + q    ) * AP + mb + g    ], ahi[mt][0], alo[mt][0]);
                split_f32(a[(ks + q    ) * AP + mb + g + 8], ahi[mt][1], alo[mt][1]);
                split_f32(a[(ks + q + 4) * AP + mb + g    ], ahi[mt][2], alo[mt][2]);
                split_f32(a[(ks + q + 4) * AP + mb + g + 8], ahi[mt][3], alo[mt][3]);
            }
            uint32_t bhi[NT][2], blo[NT][2];
            #pragma unroll
            for (int nt = 0; nt < NT; ++nt) {
                const int nb = wn * (8 * NT) + nt * 8 + g;
                split_f32(b[(ks + q    ) * BP + nb], bhi[nt][0], blo[nt][0]);
                split_f32(b[(ks + q + 4) * BP + nb], bhi[nt][1], blo[nt][1]);
            }
            #pragma unroll
            for (int mt = 0; mt < 2; ++mt)
                #pragma unroll
                for (int nt = 0; nt < NT; ++nt) {
                    mma_tf32(acc[mt][nt], alo[mt], bhi[nt]);  // lo*hi
                    mma_tf32(acc[mt][nt], ahi[mt], blo[nt]);  // hi*lo
                    mma_tf32(acc[mt][nt], ahi[mt], bhi[nt]);  // hi*hi
                }
        }
    }

    // ---- epilogue: out[m][n] = (relu?)(d[m]*acc + bias[n]) ----
    #pragma unroll
    for (int mt = 0; mt < 2; ++mt) {
        const int m = m0 + wm * 32 + mt * 16 + g;
        const float d0 = dvec[m], d1 = dvec[m + 8];
        #pragma unroll
        for (int nt = 0; nt < NT; ++nt) {
            const int n = wn * (8 * NT) + nt * 8 + 2 * q;
            const float bn0 = bias[n], bn1 = bias[n + 1];
            float v00 = fmaf(d0, acc[mt][nt][0], bn0);
            float v01 = fmaf(d0, acc[mt][nt][1], bn1);
            float v10 = fmaf(d1, acc[mt][nt][2], bn0);
            float v11 = fmaf(d1, acc[mt][nt][3], bn1);
            if (RELU) {
                v00 = fmaxf(v00, 0.f); v01 = fmaxf(v01, 0.f);
                v10 = fmaxf(v10, 0.f); v11 = fmaxf(v11, 0.f);
            }
            out[(size_t)m * NC + n]           = v00;
            out[(size_t)m * NC + n + 1]       = v01;
            out[(size_t)(m + 8) * NC + n]     = v10;
            out[(size_t)(m + 8) * NC + n + 1] = v11;
        }
    }
}

// ---------------- launch ----------------
extern "C" void kernel_launch(void* const* d_in, const int* in_sizes, int n_in,
                              void* d_out, int out_size) {
    const float* x   = (const float*)d_in[0];  // [8192, 256]
    const float* adj = (const float*)d_in[1];  // [8192, 8192]
    const float* W1  = (const float*)d_in[2];  // [256, 128]
    const float* b1  = (const float*)d_in[3];  // [128]
    const float* W2  = (const float*)d_in[4];  // [128, 64]
    const float* b2  = (const float*)d_in[5];  // [64]
    float* out = (float*)d_out;                // [8192, 64]

    float *pd, *pC1, *ph, *pC2;
    cudaGetSymbolAddress((void**)&pd,  g_d);
    cudaGetSymbolAddress((void**)&pC1, g_C1);
    cudaGetSymbolAddress((void**)&ph,  g_h);
    cudaGetSymbolAddress((void**)&pC2, g_C2);

    // dynamic smem: 4 stages * (32*72 + 32*(NC+8)) floats
    const int smem1 = 4 * (32 * 72 + 32 * (HIDDEN + 8)) * 4;  // 106496 B
    const int smem2 = 4 * (32 * 72 + 32 * (OUTC   + 8)) * 4;  //  73728 B
    cudaFuncSetAttribute(big_gemm<HIDDEN, true>,
                         cudaFuncAttributeMaxDynamicSharedMemorySize, smem1);
    cudaFuncSetAttribute(big_gemm<OUTC, false>,
                         cudaFuncAttributeMaxDynamicSharedMemorySize, smem2);

    // 1. d = rsqrt(rowsum(adj))
    rowsum_rsqrt<<<N_NODES, 256>>>(adj, pd);
    // 2. C1' = d ⊙ (x @ W1)
    small_gemm_scale<DIM_EMB, HIDDEN><<<N_NODES / 16, HIDDEN>>>(x, W1, pd, pC1);
    // 3. h = relu(d ⊙ (adj^T @ C1') + b1)
    big_gemm<HIDDEN, true><<<N_NODES / 64, 256, smem1>>>(adj, pC1, pd, b1, ph);
    // 4. C2' = d ⊙ (h @ W2)
    small_gemm_scale<HIDDEN, OUTC><<<N_NODES / 16, OUTC>>>(ph, W2, pd, pC2);
    // 5. out = d ⊙ (adj^T @ C2') + b2
    big_gemm<OUTC, false><<<N_NODES / 64, 256, smem2>>>(adj, pC2, pd, b2, out);
}